// round 1
// baseline (speedup 1.0000x reference)
#include <cuda_runtime.h>
#include <cstdint>
#include <math.h>

#define N_ROWS 4096
#define DIMS   128
#define NJ     4
#define TOPK   16
#define TN     32     // query rows per CTA
#define TM     128    // candidates per tile
#define NSTRIDE 132   // padded smem row stride (floats): 528B -> conflict-free 16B group loads

// ---------------- device scratch (static, allocation-free) ----------------
__device__ float g_finv[N_ROWS];
__device__ float g_ninv[NJ * N_ROWS];
__device__ float g_topbuf[N_ROWS * NJ * TOPK];
__device__ float g_part[16];

// ---------------- kernel 0: inverse L2 norms ----------------
__global__ void norms_kernel(const float* __restrict__ feat,
                             const float* __restrict__ negs) {
    int gw = (blockIdx.x * blockDim.x + threadIdx.x) >> 5;
    int lane = threadIdx.x & 31;
    if (gw >= N_ROWS + NJ * N_ROWS) return;
    const float4* src;
    float* dst;
    if (gw < N_ROWS) {
        src = (const float4*)(feat + (size_t)gw * DIMS);
        dst = g_finv + gw;
    } else {
        int r = gw - N_ROWS;
        src = (const float4*)(negs + (size_t)r * DIMS);
        dst = g_ninv + r;
    }
    float4 v = src[lane];
    float s = v.x * v.x + v.y * v.y + v.z * v.z + v.w * v.w;
#pragma unroll
    for (int off = 16; off; off >>= 1) s += __shfl_xor_sync(0xffffffffu, s, off);
    if (lane == 0) *dst = 1.0f / fmaxf(sqrtf(s), 1e-12f);
}

// ---------------- f32x2 helpers (FFMA2 only reachable via PTX) ----------------
__device__ __forceinline__ void lds_v2(uint64_t& a, uint64_t& b, uint32_t addr) {
    asm volatile("ld.shared.v2.u64 {%0,%1}, [%2];" : "=l"(a), "=l"(b) : "r"(addr));
}
__device__ __forceinline__ void ffma2(uint64_t& d, uint64_t a, uint64_t b) {
    asm volatile("fma.rn.f32x2 %0, %1, %2, %0;" : "+l"(d) : "l"(a), "l"(b));
}

// ---------------- kernel 1: fused normalized-GEMM + per-row top-16 ----------------
// grid: (N_ROWS/TN, NJ), block: 256
// thread map: row r = t>>3 (32 rows), column group cb = t&7; columns c = cb + 8*cc (cc=0..15)
__global__ void __launch_bounds__(256, 2)
sims_topk_kernel(const float* __restrict__ feat, const int* __restrict__ target,
                 const float* __restrict__ negs, const int* __restrict__ idxp) {
    extern __shared__ float sm[];
    float* f_s    = sm;                          // TN * NSTRIDE floats
    float* n_s    = sm + TN * NSTRIDE;           // TM * NSTRIDE floats
    float* ninv_s = n_s + TM * NSTRIDE;          // TM floats
    int*   tgt_s  = (int*)(ninv_s + TM);         // TM ints

    const int t  = threadIdx.x;
    const int nt = blockIdx.x;
    const int j  = blockIdx.y;
    const int n0 = nt * TN;
    const int r  = t >> 3;
    const int cb = t & 7;

    // stage normalized query rows
    for (int i = t; i < TN * DIMS; i += 256) {
        int rr = i >> 7, d = i & 127;
        f_s[rr * NSTRIDE + d] = feat[(size_t)(n0 + rr) * DIMS + d] * g_finv[n0 + rr];
    }
    const int  myt   = target[n0 + r];
    const bool maskj = (j == *idxp);

    uint32_t smem_u = (uint32_t)__cvta_generic_to_shared(sm);
    uint32_t fs_a   = smem_u + (uint32_t)(r * NSTRIDE) * 4u;
    uint32_t ns_a   = smem_u + (uint32_t)(TN * NSTRIDE + cb * NSTRIDE) * 4u;

    float tk[TOPK];
#pragma unroll
    for (int s = 0; s < TOPK; s++) tk[s] = -INFINITY;

    __syncthreads();

    for (int mt = 0; mt < N_ROWS / TM; ++mt) {
        const int m0 = mt * TM;
        // --- load candidate tile (coalesced float4, conflict-free smem stores) ---
        const float4* gs = (const float4*)(negs + ((size_t)j * N_ROWS + m0) * DIMS);
#pragma unroll
        for (int i = 0; i < 16; i++) {
            int id = t + 256 * i;
            int m = id >> 5, d4 = id & 31;
            float4 v = gs[m * 32 + d4];
            *(float4*)(n_s + m * NSTRIDE + d4 * 4) = v;
        }
        if (t < TM) {
            ninv_s[t] = g_ninv[j * N_ROWS + m0 + t];
            tgt_s[t]  = target[m0 + t];
        }
        __syncthreads();

        // --- 32x128 dot products, f32x2-packed along d ---
        uint64_t acc[16];
#pragma unroll
        for (int cc = 0; cc < 16; cc++) acc[cc] = 0ull;

#pragma unroll 2
        for (int d4 = 0; d4 < 32; ++d4) {
            uint64_t b01, b23;
            lds_v2(b01, b23, fs_a + d4 * 16);
            uint32_t p = ns_a + d4 * 16;
#pragma unroll
            for (int cc = 0; cc < 16; cc++) {
                uint64_t a01, a23;
                lds_v2(a01, a23, p);
                ffma2(acc[cc], a01, b01);
                ffma2(acc[cc], a23, b23);
                p += 8u * NSTRIDE * 4u;
            }
        }

        // --- scale, mask, online top-16 insert (predicated network, regs only) ---
#pragma unroll
        for (int cc = 0; cc < 16; cc++) {
            uint32_t lo, hi;
            asm("mov.b64 {%0,%1}, %2;" : "=r"(lo), "=r"(hi) : "l"(acc[cc]));
            int c = cb + cc * 8;
            float sim = (__uint_as_float(lo) + __uint_as_float(hi)) * ninv_s[c];
            if (maskj && (tgt_s[c] == myt)) sim = -1e9f;
            if (sim > tk[0]) {
#pragma unroll
                for (int s = 0; s < TOPK - 1; s++) {
                    float nxt = tk[s + 1];
                    tk[s] = (sim > nxt) ? nxt : fmaxf(sim, tk[s]);
                }
                tk[TOPK - 1] = fmaxf(sim, tk[TOPK - 1]);
            }
        }
        __syncthreads();
    }

    // --- merge 8 per-thread top-16 lists -> per-row global top-16 (sorted desc) ---
    float* mb = n_s;  // alias: tile buffer is dead now
#pragma unroll
    for (int s = 0; s < TOPK; s++) mb[r * 128 + cb * TOPK + s] = tk[s];
    __syncthreads();
    if (cb == 0) {
        float* row  = mb + r * 128;
        float* outp = g_topbuf + ((size_t)(n0 + r) * NJ + j) * TOPK;
#pragma unroll 1
        for (int k = 0; k < TOPK; k++) {
            float best = -INFINITY; int bi = 0;
            for (int q = 0; q < 128; q++) {
                float v = row[q];
                if (v > best) { best = v; bi = q; }
            }
            outp[k] = best;
            row[bi] = -INFINITY;
        }
    }
}

// ---------------- kernel 2: softmax-over-J entropy + decay, per-block partials ----------------
__global__ void entropy_kernel() {
    __shared__ float red[256];
    int n = blockIdx.x * 256 + threadIdx.x;
    const float* tb = g_topbuf + (size_t)n * (NJ * TOPK);

    float wsum = 0.f, w = 1.f;
#pragma unroll
    for (int k = 0; k < TOPK; k++) { wsum += w; w *= 0.95f; }

    float acc = 0.f; w = 1.f;
#pragma unroll
    for (int k = 0; k < TOPK; k++) {
        float l0 = tb[0 * TOPK + k] * 100.0f;
        float l1 = tb[1 * TOPK + k] * 100.0f;
        float l2 = tb[2 * TOPK + k] * 100.0f;
        float l3 = tb[3 * TOPK + k] * 100.0f;
        float m = fmaxf(fmaxf(l0, l1), fmaxf(l2, l3));
        float e0 = expf(l0 - m), e1 = expf(l1 - m), e2 = expf(l2 - m), e3 = expf(l3 - m);
        float s  = e0 + e1 + e2 + e3;
        float t1 = e0 * (l0 - m) + e1 * (l1 - m) + e2 * (l2 - m) + e3 * (l3 - m);
        float ent = t1 / s - logf(s);   // sum_j p*logp
        acc += ent * w;
        w *= 0.95f;
    }
    acc /= wsum;

    red[threadIdx.x] = acc;
    __syncthreads();
    for (int off = 128; off; off >>= 1) {
        if (threadIdx.x < off) red[threadIdx.x] += red[threadIdx.x + off];
        __syncthreads();
    }
    if (threadIdx.x == 0) g_part[blockIdx.x] = red[0];
}

// ---------------- kernel 3: deterministic final reduction ----------------
__global__ void final_kernel(float* out) {
    int lane = threadIdx.x;
    float v = (lane < 16) ? g_part[lane] : 0.f;
#pragma unroll
    for (int off = 16; off; off >>= 1) v += __shfl_xor_sync(0xffffffffu, v, off);
    if (lane == 0) out[0] = v / (float)N_ROWS + logf((float)NJ);
}

// ---------------- launch ----------------
extern "C" void kernel_launch(void* const* d_in, const int* in_sizes, int n_in,
                              void* d_out, int out_size) {
    const float* feat   = (const float*)d_in[0];
    const int*   target = (const int*)d_in[1];
    const float* negs   = (const float*)d_in[2];
    const int*   idxp   = (const int*)d_in[3];
    float*       out    = (float*)d_out;

    int smem = (TN * NSTRIDE + TM * NSTRIDE + TM + TM) * 4;  // ~85.5 KB
    cudaFuncSetAttribute(sims_topk_kernel,
                         cudaFuncAttributeMaxDynamicSharedMemorySize, smem);

    norms_kernel<<<(N_ROWS + NJ * N_ROWS) / 8, 256>>>(feat, negs);
    sims_topk_kernel<<<dim3(N_ROWS / TN, NJ), 256, smem>>>(feat, target, negs, idxp);
    entropy_kernel<<<16, 256>>>();
    final_kernel<<<1, 32>>>(out);
}

// round 3
// speedup vs baseline: 1.0373x; 1.0373x over previous
#include <cuda_runtime.h>
#include <cstdint>
#include <math.h>

#define N_ROWS 4096
#define DIMS   128
#define NJ     4
#define TOPK   16
#define TN     32     // query rows per CTA
#define TM     128    // candidates per tile
#define NSTRIDE 132   // padded smem row stride (floats): 528B (16B-divisible) -> conflict-free

// ---------------- device scratch (static, allocation-free) ----------------
__device__ float g_finv[N_ROWS];
__device__ float g_ninv[NJ * N_ROWS];
__device__ float g_topbuf[N_ROWS * NJ * TOPK];
__device__ float g_part[16];

// ---------------- kernel 0: inverse L2 norms ----------------
__global__ void norms_kernel(const float* __restrict__ feat,
                             const float* __restrict__ negs) {
    int gw = (blockIdx.x * blockDim.x + threadIdx.x) >> 5;
    int lane = threadIdx.x & 31;
    if (gw >= N_ROWS + NJ * N_ROWS) return;
    const float4* src;
    float* dst;
    if (gw < N_ROWS) {
        src = (const float4*)(feat + (size_t)gw * DIMS);
        dst = g_finv + gw;
    } else {
        int r = gw - N_ROWS;
        src = (const float4*)(negs + (size_t)r * DIMS);
        dst = g_ninv + r;
    }
    float4 v = src[lane];
    float s = v.x * v.x + v.y * v.y + v.z * v.z + v.w * v.w;
#pragma unroll
    for (int off = 16; off; off >>= 1) s += __shfl_xor_sync(0xffffffffu, s, off);
    if (lane == 0) *dst = 1.0f / fmaxf(sqrtf(s), 1e-12f);
}

// ---------------- FFMA2 (packed f32x2 fma; non-volatile so ptxas can schedule) ----------------
__device__ __forceinline__ void ffma2(uint64_t& d, uint64_t a, uint64_t b) {
    asm("fma.rn.f32x2 %0, %1, %2, %0;" : "+l"(d) : "l"(a), "l"(b));
}

// ---------------- kernel 1: fused normalized-GEMM + per-row top-16 ----------------
// grid: (N_ROWS/TN, NJ), block: 256
// thread map: row r = t>>3 (32 rows), column group cb = t&7; columns c = cb + 8*cc (cc=0..15)
__global__ void __launch_bounds__(256, 2)
sims_topk_kernel(const float* __restrict__ feat, const int* __restrict__ target,
                 const float* __restrict__ negs, const int* __restrict__ idxp) {
    extern __shared__ float sm[];
    float* f_s    = sm;                          // TN * NSTRIDE floats
    float* n_s    = sm + TN * NSTRIDE;           // TM * NSTRIDE floats
    float* ninv_s = n_s + TM * NSTRIDE;          // TM floats
    int*   tgt_s  = (int*)(ninv_s + TM);         // TM ints

    const int t  = threadIdx.x;
    const int nt = blockIdx.x;
    const int j  = blockIdx.y;
    const int n0 = nt * TN;
    const int r  = t >> 3;
    const int cb = t & 7;

    // stage normalized query rows
    for (int i = t; i < TN * DIMS; i += 256) {
        int rr = i >> 7, d = i & 127;
        f_s[rr * NSTRIDE + d] = feat[(size_t)(n0 + rr) * DIMS + d] * g_finv[n0 + rr];
    }
    const int  myt   = target[n0 + r];
    const bool maskj = (j == *idxp);

    // 16B-typed shared pointers (LDS.128, compiler-scheduled)
    const ulonglong2* fp = reinterpret_cast<const ulonglong2*>(f_s + r * NSTRIDE);
    const ulonglong2* np = reinterpret_cast<const ulonglong2*>(n_s + cb * NSTRIDE);
    const int CSTEP = 8 * NSTRIDE / 4;  // ulonglong2 stride between column groups (=264)

    float tk[TOPK];
#pragma unroll
    for (int s = 0; s < TOPK; s++) tk[s] = -INFINITY;

    __syncthreads();

    for (int mt = 0; mt < N_ROWS / TM; ++mt) {
        const int m0 = mt * TM;
        // --- load candidate tile (coalesced float4, conflict-free smem stores) ---
        const float4* gs = (const float4*)(negs + ((size_t)j * N_ROWS + m0) * DIMS);
#pragma unroll
        for (int i = 0; i < 16; i++) {
            int id = t + 256 * i;
            int m = id >> 5, d4 = id & 31;
            float4 v = gs[m * 32 + d4];
            *(float4*)(n_s + m * NSTRIDE + d4 * 4) = v;
        }
        if (t < TM) {
            ninv_s[t] = g_ninv[j * N_ROWS + m0 + t];
            tgt_s[t]  = target[m0 + t];
        }
        __syncthreads();

        // --- 32x128 dot products, f32x2-packed along d ---
        uint64_t acc[16];
#pragma unroll
        for (int cc = 0; cc < 16; cc++) acc[cc] = 0ull;

#pragma unroll 4
        for (int d4 = 0; d4 < 32; ++d4) {
            ulonglong2 b = fp[d4];
#pragma unroll
            for (int cc = 0; cc < 16; cc++) {
                ulonglong2 a = np[d4 + cc * CSTEP];
                ffma2(acc[cc], a.x, b.x);
                ffma2(acc[cc], a.y, b.y);
            }
        }

        // --- scale, mask, online top-16 insert (predicated network, regs only) ---
#pragma unroll
        for (int cc = 0; cc < 16; cc++) {
            uint32_t lo, hi;
            asm("mov.b64 {%0,%1}, %2;" : "=r"(lo), "=r"(hi) : "l"(acc[cc]));
            int c = cb + cc * 8;
            float sim = (__uint_as_float(lo) + __uint_as_float(hi)) * ninv_s[c];
            if (maskj && (tgt_s[c] == myt)) sim = -1e9f;
            if (sim > tk[0]) {
#pragma unroll
                for (int s = 0; s < TOPK - 1; s++) {
                    float nxt = tk[s + 1];
                    tk[s] = (sim > nxt) ? nxt : fmaxf(sim, tk[s]);
                }
                tk[TOPK - 1] = fmaxf(sim, tk[TOPK - 1]);
            }
        }
        __syncthreads();
    }

    // --- merge 8 sorted per-thread top-16 lists -> per-row global top-16 (desc) ---
    float* mb = n_s;  // alias: tile buffer is dead now
#pragma unroll
    for (int s = 0; s < TOPK; s++) mb[r * 128 + cb * TOPK + s] = tk[TOPK - 1 - s];  // descending
    __syncthreads();
    if (cb == 0) {
        const float* L = mb + r * 128;
        float* outp = g_topbuf + ((size_t)(n0 + r) * NJ + j) * TOPK;
        int   idx[8];
        float h[8];
#pragma unroll
        for (int q = 0; q < 8; q++) { idx[q] = 0; h[q] = L[q * TOPK]; }
#pragma unroll 1
        for (int k = 0; k < TOPK; k++) {
            float best = h[0]; int bq = 0;
#pragma unroll
            for (int q = 1; q < 8; q++) { if (h[q] > best) { best = h[q]; bq = q; } }
            outp[k] = best;
#pragma unroll
            for (int q = 0; q < 8; q++) {
                if (bq == q) {
                    idx[q]++;
                    h[q] = (idx[q] < TOPK) ? L[q * TOPK + idx[q]] : -INFINITY;
                }
            }
        }
    }
}

// ---------------- kernel 2: softmax-over-J entropy + decay, per-block partials ----------------
__global__ void entropy_kernel() {
    __shared__ float red[256];
    int n = blockIdx.x * 256 + threadIdx.x;
    const float* tb = g_topbuf + (size_t)n * (NJ * TOPK);

    float wsum = 0.f, w = 1.f;
#pragma unroll
    for (int k = 0; k < TOPK; k++) { wsum += w; w *= 0.95f; }

    float acc = 0.f; w = 1.f;
#pragma unroll
    for (int k = 0; k < TOPK; k++) {
        float l0 = tb[0 * TOPK + k] * 100.0f;
        float l1 = tb[1 * TOPK + k] * 100.0f;
        float l2 = tb[2 * TOPK + k] * 100.0f;
        float l3 = tb[3 * TOPK + k] * 100.0f;
        float m = fmaxf(fmaxf(l0, l1), fmaxf(l2, l3));
        float e0 = expf(l0 - m), e1 = expf(l1 - m), e2 = expf(l2 - m), e3 = expf(l3 - m);
        float s  = e0 + e1 + e2 + e3;
        float t1 = e0 * (l0 - m) + e1 * (l1 - m) + e2 * (l2 - m) + e3 * (l3 - m);
        float ent = t1 / s - logf(s);   // sum_j p*logp
        acc += ent * w;
        w *= 0.95f;
    }
    acc /= wsum;

    red[threadIdx.x] = acc;
    __syncthreads();
    for (int off = 128; off; off >>= 1) {
        if (threadIdx.x < off) red[threadIdx.x] += red[threadIdx.x + off];
        __syncthreads();
    }
    if (threadIdx.x == 0) g_part[blockIdx.x] = red[0];
}

// ---------------- kernel 3: deterministic final reduction ----------------
__global__ void final_kernel(float* out) {
    int lane = threadIdx.x;
    float v = (lane < 16) ? g_part[lane] : 0.f;
#pragma unroll
    for (int off = 16; off; off >>= 1) v += __shfl_xor_sync(0xffffffffu, v, off);
    if (lane == 0) out[0] = v / (float)N_ROWS + logf((float)NJ);
}

// ---------------- launch ----------------
extern "C" void kernel_launch(void* const* d_in, const int* in_sizes, int n_in,
                              void* d_out, int out_size) {
    const float* feat   = (const float*)d_in[0];
    const int*   target = (const int*)d_in[1];
    const float* negs   = (const float*)d_in[2];
    const int*   idxp   = (const int*)d_in[3];
    float*       out    = (float*)d_out;

    int smem = (TN * NSTRIDE + TM * NSTRIDE + TM + TM) * 4;  // ~85.5 KB
    cudaFuncSetAttribute(sims_topk_kernel,
                         cudaFuncAttributeMaxDynamicSharedMemorySize, smem);

    norms_kernel<<<(N_ROWS + NJ * N_ROWS) / 8, 256>>>(feat, negs);
    sims_topk_kernel<<<dim3(N_ROWS / TN, NJ), 256, smem>>>(feat, target, negs, idxp);
    entropy_kernel<<<16, 256>>>();
    final_kernel<<<1, 32>>>(out);
}

// round 4
// speedup vs baseline: 2.7364x; 2.6380x over previous
#include <cuda_runtime.h>
#include <cstdint>
#include <math.h>

#define N_ROWS 4096
#define DIMS   128
#define NJ     4
#define TOPK   16
#define KC     32      // k-chunk for GEMM staging
#define LSTR   132     // smem d-line stride in floats

// ---------------- device scratch (static, allocation-free) ----------------
__device__ float g_finv[N_ROWS];
__device__ float g_ninv[NJ * N_ROWS];
__device__ float g_sims[(size_t)NJ * N_ROWS * N_ROWS];   // 256 MB
__device__ float g_topbuf[N_ROWS * NJ * TOPK];
__device__ float g_part[16];

// ---------------- kernel 0: inverse L2 norms ----------------
__global__ void norms_kernel(const float* __restrict__ feat,
                             const float* __restrict__ negs) {
    int gw = (blockIdx.x * blockDim.x + threadIdx.x) >> 5;
    int lane = threadIdx.x & 31;
    if (gw >= N_ROWS + NJ * N_ROWS) return;
    const float4* src;
    float* dst;
    if (gw < N_ROWS) {
        src = (const float4*)(feat + (size_t)gw * DIMS);
        dst = g_finv + gw;
    } else {
        int r = gw - N_ROWS;
        src = (const float4*)(negs + (size_t)r * DIMS);
        dst = g_ninv + r;
    }
    float4 v = src[lane];
    float s = v.x * v.x + v.y * v.y + v.z * v.z + v.w * v.w;
#pragma unroll
    for (int off = 16; off; off >>= 1) s += __shfl_xor_sync(0xffffffffu, s, off);
    if (lane == 0) *dst = 1.0f / fmaxf(sqrtf(s), 1e-12f);
}

// ---------------- packed f32x2 helpers ----------------
__device__ __forceinline__ void ffma2(uint64_t& d, uint64_t a, uint64_t b) {
    asm("fma.rn.f32x2 %0, %1, %2, %0;" : "+l"(d) : "l"(a), "l"(b));
}
__device__ __forceinline__ uint64_t dup2(float x) {
    uint64_t r;
    asm("mov.b64 %0, {%1, %1};" : "=l"(r) : "f"(x));
    return r;
}

// ---------------- kernel 1: normalized GEMM -> g_sims ----------------
// grid (32 colTiles, 32 rowTiles, NJ), block 256 (16 tx x 16 ty)
// thread microtile: rows {4ty..+3, 64+4ty..+3} x cols {4tx..+3, 64+4tx..+3}
__global__ void __launch_bounds__(256, 2)
gemm_kernel(const float* __restrict__ feat, const float* __restrict__ negs) {
    __shared__ float A_s[KC * LSTR];   // [d][row] rows = queries
    __shared__ float B_s[KC * LSTR];   // [d][col] cols = candidates

    const int t  = threadIdx.x;
    const int tx = t & 15;
    const int ty = t >> 4;
    const int m0 = blockIdx.x * 128;   // candidate cols
    const int n0 = blockIdx.y * 128;   // query rows
    const int j  = blockIdx.z;

    const float* Bg   = negs + (size_t)j * N_ROWS * DIMS;
    const float* ninv = g_ninv + j * N_ROWS;

    uint64_t acc[8][4];
#pragma unroll
    for (int c = 0; c < 8; c++)
#pragma unroll
        for (int p = 0; p < 4; p++) acc[c][p] = 0ull;

    for (int kc = 0; kc < DIMS / KC; ++kc) {
        // ---- fill (transposed, normalized) ----
#pragma unroll
        for (int i = 0; i < 4; i++) {
            int id  = t + 256 * i;       // 0..1023
            int row = id >> 3;
            int d4  = id & 7;
            float4 va = *(const float4*)(feat + (size_t)(n0 + row) * DIMS + kc * KC + d4 * 4);
            float  sa = g_finv[n0 + row];
            A_s[(d4 * 4 + 0) * LSTR + row] = va.x * sa;
            A_s[(d4 * 4 + 1) * LSTR + row] = va.y * sa;
            A_s[(d4 * 4 + 2) * LSTR + row] = va.z * sa;
            A_s[(d4 * 4 + 3) * LSTR + row] = va.w * sa;
            float4 vb = *(const float4*)(Bg + (size_t)(m0 + row) * DIMS + kc * KC + d4 * 4);
            float  sb = ninv[m0 + row];
            B_s[(d4 * 4 + 0) * LSTR + row] = vb.x * sb;
            B_s[(d4 * 4 + 1) * LSTR + row] = vb.y * sb;
            B_s[(d4 * 4 + 2) * LSTR + row] = vb.z * sb;
            B_s[(d4 * 4 + 3) * LSTR + row] = vb.w * sb;
        }
        __syncthreads();

        // ---- compute ----
#pragma unroll 4
        for (int d = 0; d < KC; ++d) {
            const float* al = A_s + d * LSTR;
            const float* bl = B_s + d * LSTR;
            ulonglong2 ra = *(const ulonglong2*)(al + 4 * ty);        // rows 4ty..+3
            ulonglong2 rb = *(const ulonglong2*)(al + 64 + 4 * ty);   // rows 64+4ty..+3
            float4 cA = *(const float4*)(bl + 4 * tx);                // cols 4tx..+3
            float4 cB = *(const float4*)(bl + 64 + 4 * tx);           // cols 64+4tx..+3
            float cs[8] = {cA.x, cA.y, cA.z, cA.w, cB.x, cB.y, cB.z, cB.w};
#pragma unroll
            for (int c = 0; c < 8; c++) {
                uint64_t cd = dup2(cs[c]);
                ffma2(acc[c][0], ra.x, cd);
                ffma2(acc[c][1], ra.y, cd);
                ffma2(acc[c][2], rb.x, cd);
                ffma2(acc[c][3], rb.y, cd);
            }
        }
        __syncthreads();
    }

    // ---- epilogue: store 8x8 microtile ----
    float* out = g_sims + ((size_t)j * N_ROWS + n0) * N_ROWS + m0;
#pragma unroll
    for (int p = 0; p < 4; p++) {
        int rbase = (p < 2) ? (4 * ty + 2 * p) : (64 + 4 * ty + 2 * (p - 2));
        float lo[8], hi[8];
#pragma unroll
        for (int c = 0; c < 8; c++) {
            uint32_t l, h;
            asm("mov.b64 {%0,%1}, %2;" : "=r"(l), "=r"(h) : "l"(acc[c][p]));
            lo[c] = __uint_as_float(l);
            hi[c] = __uint_as_float(h);
        }
        float4 v;
        v = make_float4(lo[0], lo[1], lo[2], lo[3]);
        *(float4*)(out + (size_t)rbase * N_ROWS + 4 * tx) = v;
        v = make_float4(lo[4], lo[5], lo[6], lo[7]);
        *(float4*)(out + (size_t)rbase * N_ROWS + 64 + 4 * tx) = v;
        v = make_float4(hi[0], hi[1], hi[2], hi[3]);
        *(float4*)(out + (size_t)(rbase + 1) * N_ROWS + 4 * tx) = v;
        v = make_float4(hi[4], hi[5], hi[6], hi[7]);
        *(float4*)(out + (size_t)(rbase + 1) * N_ROWS + 64 + 4 * tx) = v;
    }
}

// ---------------- warp top-16 selection over a smem buffer ----------------
// Selects the 16 largest of bw[0..cnt) (cnt<=128), writes them (desc) to
// bw[0..15], optionally to outp[0..15]. Returns the 16th largest.
__device__ __forceinline__ float warp_select16(float* bw, int cnt, int lane,
                                               float* outp) {
    float x0 = (lane < cnt)      ? bw[lane]      : -INFINITY;
    float x1 = (lane + 32 < cnt) ? bw[lane + 32] : -INFINITY;
    float x2 = (lane + 64 < cnt) ? bw[lane + 64] : -INFINITY;
    float x3 = (lane + 96 < cnt) ? bw[lane + 96] : -INFINITY;
    float wm = -INFINITY;
#pragma unroll 1
    for (int k = 0; k < TOPK; k++) {
        float lm = fmaxf(fmaxf(x0, x1), fmaxf(x2, x3));
        wm = lm;
#pragma unroll
        for (int off = 16; off; off >>= 1)
            wm = fmaxf(wm, __shfl_xor_sync(0xffffffffu, wm, off));
        unsigned b = __ballot_sync(0xffffffffu, lm == wm);
        int leader = __ffs(b) - 1;
        if (lane == leader) {
            if      (x0 == wm) x0 = -INFINITY;
            else if (x1 == wm) x1 = -INFINITY;
            else if (x2 == wm) x2 = -INFINITY;
            else               x3 = -INFINITY;
        }
        if (lane == 0) {
            bw[k] = wm;
            if (outp) outp[k] = wm;
        }
    }
    return wm;  // 16th largest
}

// ---------------- kernel 2: per-(row,j) top-16 over 4096 candidates ----------------
// grid (N_ROWS/8, NJ), block 256 (8 warps, warp = one row)
__global__ void __launch_bounds__(256)
topk_kernel(const int* __restrict__ target, const int* __restrict__ idxp) {
    __shared__ float buf[8][128];
    const int w    = threadIdx.x >> 5;
    const int lane = threadIdx.x & 31;
    const int row  = blockIdx.x * 8 + w;
    const int j    = blockIdx.y;
    const bool maskj = (j == *idxp);
    const int  myt   = target[row];
    const float* rowp = g_sims + ((size_t)j * N_ROWS + row) * N_ROWS;
    float* bw = buf[w];
    const unsigned lmask = (1u << lane) - 1u;

    float tau = -INFINITY;
    int   cnt = 0;

#pragma unroll 1
    for (int it = 0; it < N_ROWS / 128; ++it) {
        int c0 = it * 128 + lane * 4;
        float4 v = *(const float4*)(rowp + c0);
        if (maskj) {
            int4 tg = *(const int4*)(target + c0);
            if (tg.x == myt) v.x = -1e9f;
            if (tg.y == myt) v.y = -1e9f;
            if (tg.z == myt) v.z = -1e9f;
            if (tg.w == myt) v.w = -1e9f;
        }
        float vv[4] = {v.x, v.y, v.z, v.w};
#pragma unroll
        for (int e = 0; e < 4; e++) {
            bool p = vv[e] > tau;
            unsigned m = __ballot_sync(0xffffffffu, p);
            if (m) {
                if (p) bw[cnt + __popc(m & lmask)] = vv[e];
                cnt += __popc(m);
                __syncwarp();
                if (cnt > 96) {           // compact: keep exact top-16, tighten tau
                    tau = warp_select16(bw, cnt, lane, nullptr);
                    cnt = TOPK;
                    __syncwarp();
                }
            }
        }
    }
    float* outp = g_topbuf + ((size_t)row * NJ + j) * TOPK;
    warp_select16(bw, cnt, lane, outp);
}

// ---------------- kernel 3: softmax-over-J entropy + decay, per-block partials ----------------
__global__ void entropy_kernel() {
    __shared__ float red[256];
    int n = blockIdx.x * 256 + threadIdx.x;
    const float* tb = g_topbuf + (size_t)n * (NJ * TOPK);

    float wsum = 0.f, w = 1.f;
#pragma unroll
    for (int k = 0; k < TOPK; k++) { wsum += w; w *= 0.95f; }

    float acc = 0.f; w = 1.f;
#pragma unroll
    for (int k = 0; k < TOPK; k++) {
        float l0 = tb[0 * TOPK + k] * 100.0f;
        float l1 = tb[1 * TOPK + k] * 100.0f;
        float l2 = tb[2 * TOPK + k] * 100.0f;
        float l3 = tb[3 * TOPK + k] * 100.0f;
        float m = fmaxf(fmaxf(l0, l1), fmaxf(l2, l3));
        float e0 = expf(l0 - m), e1 = expf(l1 - m), e2 = expf(l2 - m), e3 = expf(l3 - m);
        float s  = e0 + e1 + e2 + e3;
        float t1 = e0 * (l0 - m) + e1 * (l1 - m) + e2 * (l2 - m) + e3 * (l3 - m);
        float ent = t1 / s - logf(s);   // sum_j p*logp
        acc += ent * w;
        w *= 0.95f;
    }
    acc /= wsum;

    red[threadIdx.x] = acc;
    __syncthreads();
    for (int off = 128; off; off >>= 1) {
        if (threadIdx.x < off) red[threadIdx.x] += red[threadIdx.x + off];
        __syncthreads();
    }
    if (threadIdx.x == 0) g_part[blockIdx.x] = red[0];
}

// ---------------- kernel 4: deterministic final reduction ----------------
__global__ void final_kernel(float* out) {
    int lane = threadIdx.x;
    float v = (lane < 16) ? g_part[lane] : 0.f;
#pragma unroll
    for (int off = 16; off; off >>= 1) v += __shfl_xor_sync(0xffffffffu, v, off);
    if (lane == 0) out[0] = v / (float)N_ROWS + logf((float)NJ);
}

// ---------------- launch ----------------
extern "C" void kernel_launch(void* const* d_in, const int* in_sizes, int n_in,
                              void* d_out, int out_size) {
    const float* feat   = (const float*)d_in[0];
    const int*   target = (const int*)d_in[1];
    const float* negs   = (const float*)d_in[2];
    const int*   idxp   = (const int*)d_in[3];
    float*       out    = (float*)d_out;

    norms_kernel<<<(N_ROWS + NJ * N_ROWS) / 8, 256>>>(feat, negs);
    gemm_kernel<<<dim3(N_ROWS / 128, N_ROWS / 128, NJ), 256>>>(feat, negs);
    topk_kernel<<<dim3(N_ROWS / 8, NJ), 256>>>(target, idxp);
    entropy_kernel<<<16, 256>>>();
    final_kernel<<<1, 32>>>(out);
}

// round 8
// speedup vs baseline: 4.9373x; 1.8043x over previous
#include <cuda_runtime.h>
#include <cuda_bf16.h>
#include <cstdint>
#include <math.h>

#define N_ROWS 4096
#define DIMS   128
#define NJ     4
#define TOPK   16

#define SMEM_SWZ(o) ((o) ^ (((o) >> 3) & 0x70))

// smem map (bytes): 6 x 32KB bf16 tiles = 192KB
#define SM_AHI  0
#define SM_ALO  32768
#define SM_BHI0 65536
#define SM_BLO0 98304
#define SM_BHI1 131072
#define SM_BLO1 163840
#define SM_TOTAL 196608

// ---------------- device scratch (static, allocation-free) ----------------
__device__ __nv_bfloat16 g_fhi[N_ROWS * DIMS];
__device__ __nv_bfloat16 g_flo[N_ROWS * DIMS];
__device__ __nv_bfloat16 g_nhi[(size_t)NJ * N_ROWS * DIMS];
__device__ __nv_bfloat16 g_nlo[(size_t)NJ * N_ROWS * DIMS];
__device__ float g_sims[(size_t)NJ * N_ROWS * N_ROWS];   // 256 MB
__device__ float g_topbuf[N_ROWS * NJ * TOPK];
__device__ float g_part[32];

// ---------------- PTX helpers (base-arch portable: no tcgen05) ----------------
__device__ __forceinline__ uint32_t smem_u32(const void* p) {
    uint32_t a;
    asm("{ .reg .u64 t; cvta.to.shared.u64 t, %1; cvt.u32.u64 %0, t; }" : "=r"(a) : "l"(p));
    return a;
}
__device__ __forceinline__ void ldsm4(uint32_t* r, uint32_t a) {
    asm volatile("ldmatrix.sync.aligned.m8n8.x4.shared.b16 {%0,%1,%2,%3}, [%4];"
                 : "=r"(r[0]), "=r"(r[1]), "=r"(r[2]), "=r"(r[3]) : "r"(a));
}
__device__ __forceinline__ void ldsm2(uint32_t* r, uint32_t a) {
    asm volatile("ldmatrix.sync.aligned.m8n8.x2.shared.b16 {%0,%1}, [%2];"
                 : "=r"(r[0]), "=r"(r[1]) : "r"(a));
}
__device__ __forceinline__ void mma16816(float* c, const uint32_t* a, const uint32_t* b) {
    asm volatile(
        "mma.sync.aligned.m16n8k16.row.col.f32.bf16.bf16.f32 "
        "{%0,%1,%2,%3}, {%4,%5,%6,%7}, {%8,%9}, {%0,%1,%2,%3};"
        : "+f"(c[0]), "+f"(c[1]), "+f"(c[2]), "+f"(c[3])
        : "r"(a[0]), "r"(a[1]), "r"(a[2]), "r"(a[3]), "r"(b[0]), "r"(b[1]));
}

// Byte offset of (row, col) in a 128x128 bf16 tile stored as 8-row x 128B
// blocked atoms with SW128 XOR swizzle. col must be a multiple of 8.
__device__ __forceinline__ uint32_t toff(int row, int col) {
    return (uint32_t)(((row >> 3) + (col >> 6) * 16) * 1024 + (row & 7) * 128 +
                      ((((col >> 3) & 7) ^ (row & 7)) * 16));
}

// Stage a 128x128 bf16 tile (row-major in gmem) into swizzled smem via cp.async.
__device__ __forceinline__ void stage_async(uint32_t sdst,
                                            const __nv_bfloat16* __restrict__ g,
                                            int t) {
#pragma unroll
    for (int i = 0; i < 8; i++) {
        int c = t + 256 * i;              // 0..2047 16B chunks
        int row = c >> 4, kch = c & 15;
        uint32_t dst = sdst + toff(row, kch * 8);
        const void* src = g + row * DIMS + kch * 8;
        asm volatile("cp.async.cg.shared.global [%0], [%1], 16;" :: "r"(dst), "l"(src));
    }
}

// ---------------- kernel 0: normalize + bf16 hi/lo split ----------------
__global__ void convert_kernel(const float* __restrict__ feat,
                               const float* __restrict__ negs) {
    int gw = (blockIdx.x * blockDim.x + threadIdx.x) >> 5;
    int lane = threadIdx.x & 31;
    if (gw >= N_ROWS + NJ * N_ROWS) return;
    const float* src;
    __nv_bfloat16 *dh, *dl;
    if (gw < N_ROWS) {
        src = feat + (size_t)gw * DIMS;
        dh = g_fhi + (size_t)gw * DIMS;
        dl = g_flo + (size_t)gw * DIMS;
    } else {
        int r = gw - N_ROWS;
        src = negs + (size_t)r * DIMS;
        dh = g_nhi + (size_t)r * DIMS;
        dl = g_nlo + (size_t)r * DIMS;
    }
    float4 v = ((const float4*)src)[lane];
    float s = v.x * v.x + v.y * v.y + v.z * v.z + v.w * v.w;
#pragma unroll
    for (int off = 16; off; off >>= 1) s += __shfl_xor_sync(0xffffffffu, s, off);
    float rinv = 1.0f / fmaxf(sqrtf(s), 1e-12f);
    float x[4] = {v.x * rinv, v.y * rinv, v.z * rinv, v.w * rinv};
    __nv_bfloat16 h[4], l[4];
#pragma unroll
    for (int e = 0; e < 4; e++) {
        h[e] = __float2bfloat16(x[e]);
        l[e] = __float2bfloat16(x[e] - __bfloat162float(h[e]));
    }
    __nv_bfloat162* dh2 = (__nv_bfloat162*)(dh + 4 * lane);
    __nv_bfloat162* dl2 = (__nv_bfloat162*)(dl + 4 * lane);
    dh2[0] = __nv_bfloat162{h[0], h[1]};
    dh2[1] = __nv_bfloat162{h[2], h[3]};
    dl2[0] = __nv_bfloat162{l[0], l[1]};
    dl2[1] = __nv_bfloat162{l[2], l[3]};
}

// ---------------- kernel 1: HMMA GEMM (bf16 hi/lo 3-term) -> g_sims ----------------
// grid (32 queryTiles, NJ), block 256 (8 warps; warp tile 64q x 32cand)
__global__ void __launch_bounds__(256, 1) gemm_kernel() {
    extern __shared__ char smem[];
    const int t = threadIdx.x, wid = t >> 5, lane = t & 31;
    const int n0 = blockIdx.x * 128;
    const int j  = blockIdx.y;
    const uint32_t sb = smem_u32(smem);

    const __nv_bfloat16* nh = g_nhi + (size_t)j * N_ROWS * DIMS;
    const __nv_bfloat16* nl = g_nlo + (size_t)j * N_ROWS * DIMS;
    float* simsj = g_sims + (size_t)j * N_ROWS * N_ROWS;

    // prologue: A (queries, fixed) + B tile 0
    stage_async(sb + SM_AHI, g_fhi + (size_t)n0 * DIMS, t);
    stage_async(sb + SM_ALO, g_flo + (size_t)n0 * DIMS, t);
    stage_async(sb + SM_BHI0, nh, t);
    stage_async(sb + SM_BLO0, nl, t);
    asm volatile("cp.async.commit_group;");

    const int qoff = (wid >> 2) * 64;
    const int coff = (wid & 3) * 32;
    const int a_r  = ((lane >> 3) & 1) * 8 + (lane & 7);
    const int a_c8 = (lane >> 4) * 8;
    const int b_r  = (lane & 7);
    const int b_c8 = ((lane >> 3) & 1) * 8;

#pragma unroll 1
    for (int it = 0; it < 32; ++it) {
        const int cur = it & 1;
        if (it < 31) {
            stage_async(sb + (cur ? SM_BHI0 : SM_BHI1), nh + (size_t)(it + 1) * 128 * DIMS, t);
            stage_async(sb + (cur ? SM_BLO0 : SM_BLO1), nl + (size_t)(it + 1) * 128 * DIMS, t);
            asm volatile("cp.async.commit_group;");
            asm volatile("cp.async.wait_group 1;");
        } else {
            asm volatile("cp.async.wait_group 0;");
        }
        __syncthreads();

        const uint32_t bh_base = sb + (cur ? SM_BHI1 : SM_BHI0);
        const uint32_t bl_base = sb + (cur ? SM_BLO1 : SM_BLO0);

        float c[4][4][4];
#pragma unroll
        for (int mi = 0; mi < 4; mi++)
#pragma unroll
            for (int ni = 0; ni < 4; ni++)
#pragma unroll
                for (int e = 0; e < 4; e++) c[mi][ni][e] = 0.f;

#pragma unroll
        for (int kc = 0; kc < 8; ++kc) {
            uint32_t ah[4][4], al[4][4], bh[4][2], bl[4][2];
#pragma unroll
            for (int mi = 0; mi < 4; mi++) {
                uint32_t off = toff(qoff + mi * 16 + a_r, kc * 16 + a_c8);
                ldsm4(ah[mi], sb + SM_AHI + off);
                ldsm4(al[mi], sb + SM_ALO + off);
            }
#pragma unroll
            for (int ni = 0; ni < 4; ni++) {
                uint32_t off = toff(coff + ni * 8 + b_r, kc * 16 + b_c8);
                ldsm2(bh[ni], bh_base + off);
                ldsm2(bl[ni], bl_base + off);
            }
#pragma unroll
            for (int mi = 0; mi < 4; mi++)
#pragma unroll
                for (int ni = 0; ni < 4; ni++) mma16816(c[mi][ni], ah[mi], bh[ni]);
#pragma unroll
            for (int mi = 0; mi < 4; mi++)
#pragma unroll
                for (int ni = 0; ni < 4; ni++) mma16816(c[mi][ni], ah[mi], bl[ni]);
#pragma unroll
            for (int mi = 0; mi < 4; mi++)
#pragma unroll
                for (int ni = 0; ni < 4; ni++) mma16816(c[mi][ni], al[mi], bh[ni]);
        }
        __syncthreads();   // smem reads done before next iter's cp.async overwrite

        // epilogue: C frag -> sims[j][q][cand] (coalesced STG.64)
        const int cand0 = it * 128 + coff;
#pragma unroll
        for (int mi = 0; mi < 4; mi++) {
            const int q = n0 + qoff + mi * 16 + (lane >> 2);
#pragma unroll
            for (int ni = 0; ni < 4; ni++) {
                const int cd = cand0 + ni * 8 + (lane & 3) * 2;
                *(float2*)&simsj[(size_t)q * N_ROWS + cd] =
                    make_float2(c[mi][ni][0], c[mi][ni][1]);
                *(float2*)&simsj[(size_t)(q + 8) * N_ROWS + cd] =
                    make_float2(c[mi][ni][2], c[mi][ni][3]);
            }
        }
    }
}

// ---------------- warp top-16 selection over a smem buffer ----------------
__device__ __forceinline__ float warp_select16(float* bw, int cnt, int lane,
                                               float* outp) {
    float x0 = (lane < cnt)      ? bw[lane]      : -INFINITY;
    float x1 = (lane + 32 < cnt) ? bw[lane + 32] : -INFINITY;
    float x2 = (lane + 64 < cnt) ? bw[lane + 64] : -INFINITY;
    float x3 = (lane + 96 < cnt) ? bw[lane + 96] : -INFINITY;
    float wm = -INFINITY;
#pragma unroll 1
    for (int k = 0; k < TOPK; k++) {
        float lm = fmaxf(fmaxf(x0, x1), fmaxf(x2, x3));
        wm = lm;
#pragma unroll
        for (int off = 16; off; off >>= 1)
            wm = fmaxf(wm, __shfl_xor_sync(0xffffffffu, wm, off));
        unsigned b = __ballot_sync(0xffffffffu, lm == wm);
        int leader = __ffs(b) - 1;
        if (lane == leader) {
            if      (x0 == wm) x0 = -INFINITY;
            else if (x1 == wm) x1 = -INFINITY;
            else if (x2 == wm) x2 = -INFINITY;
            else               x3 = -INFINITY;
        }
        if (lane == 0) {
            bw[k] = wm;
            if (outp) outp[k] = wm;
        }
    }
    return wm;
}

// ---------------- kernel 2: per-(row,j) top-16 over 4096 candidates ----------------
__global__ void __launch_bounds__(256)
topk_kernel(const int* __restrict__ target, const int* __restrict__ idxp) {
    __shared__ float buf[8][128];
    const int w    = threadIdx.x >> 5;
    const int lane = threadIdx.x & 31;
    const int row  = blockIdx.x * 8 + w;
    const int j    = blockIdx.y;
    const bool maskj = (j == *idxp);
    const int  myt   = target[row];
    const float* rowp = g_sims + ((size_t)j * N_ROWS + row) * N_ROWS;
    float* bw = buf[w];
    const unsigned lmask = (1u << lane) - 1u;

    float tau = -INFINITY;
    int   cnt = 0;

#pragma unroll 1
    for (int it = 0; it < N_ROWS / 128; ++it) {
        int c0 = it * 128 + lane * 4;
        float4 v = *(const float4*)(rowp + c0);
        if (maskj) {
            int4 tg = *(const int4*)(target + c0);
            if (tg.x == myt) v.x = -1e9f;
            if (tg.y == myt) v.y = -1e9f;
            if (tg.z == myt) v.z = -1e9f;
            if (tg.w == myt) v.w = -1e9f;
        }
        float vv[4] = {v.x, v.y, v.z, v.w};
#pragma unroll
        for (int e = 0; e < 4; e++) {
            bool p = vv[e] > tau;
            unsigned m = __ballot_sync(0xffffffffu, p);
            if (m) {
                if (p) bw[cnt + __popc(m & lmask)] = vv[e];
                cnt += __popc(m);
                __syncwarp();
                if (cnt > 96) {
                    tau = warp_select16(bw, cnt, lane, nullptr);
                    cnt = TOPK;
                    __syncwarp();
                }
            }
        }
    }
    float* outp = g_topbuf + ((size_t)row * NJ + j) * TOPK;
    warp_select16(bw, cnt, lane, outp);
}

// ---------------- kernel 3: entropy + decay, per-block partials ----------------
__global__ void entropy_kernel() {
    __shared__ float red[128];
    int n = blockIdx.x * 128 + threadIdx.x;
    const float* tb = g_topbuf + (size_t)n * (NJ * TOPK);

    float wsum = 0.f, w = 1.f;
#pragma unroll
    for (int k = 0; k < TOPK; k++) { wsum += w; w *= 0.95f; }

    float acc = 0.f; w = 1.f;
#pragma unroll
    for (int k = 0; k < TOPK; k++) {
        float l0 = tb[0 * TOPK + k] * 100.0f;
        float l1 = tb[1 * TOPK + k] * 100.0f;
        float l2 = tb[2 * TOPK + k] * 100.0f;
        float l3 = tb[3 * TOPK + k] * 100.0f;
        float m = fmaxf(fmaxf(l0, l1), fmaxf(l2, l3));
        float e0 = expf(l0 - m), e1 = expf(l1 - m), e2 = expf(l2 - m), e3 = expf(l3 - m);
        float s  = e0 + e1 + e2 + e3;
        float t1 = e0 * (l0 - m) + e1 * (l1 - m) + e2 * (l2 - m) + e3 * (l3 - m);
        float ent = t1 / s - logf(s);
        acc += ent * w;
        w *= 0.95f;
    }
    acc /= wsum;

    red[threadIdx.x] = acc;
    __syncthreads();
    for (int off = 64; off; off >>= 1) {
        if (threadIdx.x < off) red[threadIdx.x] += red[threadIdx.x + off];
        __syncthreads();
    }
    if (threadIdx.x == 0) g_part[blockIdx.x] = red[0];
}

// ---------------- kernel 4: deterministic final reduction ----------------
__global__ void final_kernel(float* out) {
    int lane = threadIdx.x;
    float v = g_part[lane];
#pragma unroll
    for (int off = 16; off; off >>= 1) v += __shfl_xor_sync(0xffffffffu, v, off);
    if (lane == 0) out[0] = v / (float)N_ROWS + logf((float)NJ);
}

// ---------------- launch ----------------
extern "C" void kernel_launch(void* const* d_in, const int* in_sizes, int n_in,
                              void* d_out, int out_size) {
    const float* feat   = (const float*)d_in[0];
    const int*   target = (const int*)d_in[1];
    const float* negs   = (const float*)d_in[2];
    const int*   idxp   = (const int*)d_in[3];
    float*       out    = (float*)d_out;

    cudaFuncSetAttribute(gemm_kernel,
                         cudaFuncAttributeMaxDynamicSharedMemorySize, SM_TOTAL);

    convert_kernel<<<(N_ROWS + NJ * N_ROWS) / 8, 256>>>(feat, negs);
    gemm_kernel<<<dim3(N_ROWS / 128, NJ), 256, SM_TOTAL>>>();
    topk_kernel<<<dim3(N_ROWS / 8, NJ), 256>>>(target, idxp);
    entropy_kernel<<<32, 128>>>();
    final_kernel<<<1, 32>>>(out);
}